// round 3
// baseline (speedup 1.0000x reference)
#include <cuda_runtime.h>

// Problem constants
#define Bb 2
#define Ss 2048
#define Ee 1024
#define Hh 16
#define Dd 64
#define BHh (Bb*Hh)

// Scratch (device globals -- no allocations allowed)
__device__ float g_q [BHh * Ss * Dd];   // [B*H][S][D]
__device__ float g_k [BHh * Ss * Dd];
__device__ float g_v [BHh * Ss * Dd];
__device__ float g_ao[Bb * Ss * Ee];    // attention output, [B,S,E]

// ---------------------------------------------------------------------------
// SGEMM: C[M,N] = A[M,K] @ W[K,N] + bias
//   MODE 0: scatter columns into Q/K/V [B,H,S,D] layout
//   MODE 1: plain write to Cout
// Tiles: 128x128, BK=16, 256 threads, 8x8 per thread, register prefetch.
// ---------------------------------------------------------------------------
template<int MODE>
__global__ void __launch_bounds__(256)
sgemm_kernel(const float* __restrict__ A, const float* __restrict__ W,
             const float* __restrict__ bias, float* __restrict__ Cout,
             float* __restrict__ Qd, float* __restrict__ Kd, float* __restrict__ Vd,
             int M, int N, int K)
{
    __shared__ float As[16 * 132];   // [k][m], padded stride 132
    __shared__ float Bs[16 * 128];   // [k][n]

    const int tid = threadIdx.x;
    const int tx  = tid & 15;        // 16 col groups of 8
    const int ty  = tid >> 4;        // 16 row groups of 8
    const int row0 = blockIdx.y * 128;
    const int col0 = blockIdx.x * 128;

    float acc[8][8];
    #pragma unroll
    for (int i = 0; i < 8; i++)
        #pragma unroll
        for (int j = 0; j < 8; j++) acc[i][j] = 0.f;

    // global->smem mapping (2 float4 each for A and B per thread)
    const int f0 = tid, f1 = tid + 256;
    const int ar0 = f0 >> 2, ak0 = (f0 & 3) * 4;
    const int ar1 = f1 >> 2, ak1 = (f1 & 3) * 4;
    const int br0 = f0 >> 5, bc0 = (f0 & 31) * 4;
    const int br1 = f1 >> 5, bc1 = (f1 & 31) * 4;

    float4 pa0, pa1, pb0, pb1;
    pa0 = *(const float4*)(A + (row0 + ar0) * K + ak0);
    pa1 = *(const float4*)(A + (row0 + ar1) * K + ak1);
    pb0 = *(const float4*)(W + br0 * N + col0 + bc0);
    pb1 = *(const float4*)(W + br1 * N + col0 + bc1);

    const int ntiles = K / 16;
    for (int t = 0; t < ntiles; t++) {
        // store prefetched tile to smem (A transposed)
        As[(ak0+0)*132 + ar0] = pa0.x;
        As[(ak0+1)*132 + ar0] = pa0.y;
        As[(ak0+2)*132 + ar0] = pa0.z;
        As[(ak0+3)*132 + ar0] = pa0.w;
        As[(ak1+0)*132 + ar1] = pa1.x;
        As[(ak1+1)*132 + ar1] = pa1.y;
        As[(ak1+2)*132 + ar1] = pa1.z;
        As[(ak1+3)*132 + ar1] = pa1.w;
        *(float4*)&Bs[br0*128 + bc0] = pb0;
        *(float4*)&Bs[br1*128 + bc1] = pb1;
        __syncthreads();

        if (t + 1 < ntiles) {
            const float* Ap = A + (t + 1) * 16;
            const float* Wp = W + (size_t)(t + 1) * 16 * N;
            pa0 = *(const float4*)(Ap + (row0 + ar0) * K + ak0);
            pa1 = *(const float4*)(Ap + (row0 + ar1) * K + ak1);
            pb0 = *(const float4*)(Wp + br0 * N + col0 + bc0);
            pb1 = *(const float4*)(Wp + br1 * N + col0 + bc1);
        }

        #pragma unroll
        for (int k = 0; k < 16; k++) {
            float4 a0 = *(float4*)&As[k*132 + ty*8];
            float4 a1 = *(float4*)&As[k*132 + ty*8 + 4];
            float4 b0 = *(float4*)&Bs[k*128 + tx*8];
            float4 b1 = *(float4*)&Bs[k*128 + tx*8 + 4];
            float a[8]  = {a0.x,a0.y,a0.z,a0.w,a1.x,a1.y,a1.z,a1.w};
            float bb[8] = {b0.x,b0.y,b0.z,b0.w,b1.x,b1.y,b1.z,b1.w};
            #pragma unroll
            for (int i = 0; i < 8; i++)
                #pragma unroll
                for (int j = 0; j < 8; j++)
                    acc[i][j] = fmaf(a[i], bb[j], acc[i][j]);
        }
        __syncthreads();
    }

    // epilogue
    #pragma unroll
    for (int i = 0; i < 8; i++) {
        int r = row0 + ty*8 + i;
        #pragma unroll
        for (int jj = 0; jj < 8; jj += 4) {
            int cg = col0 + tx*8 + jj;
            float4 v;
            v.x = acc[i][jj+0] + bias[cg+0];
            v.y = acc[i][jj+1] + bias[cg+1];
            v.z = acc[i][jj+2] + bias[cg+2];
            v.w = acc[i][jj+3] + bias[cg+3];
            if (MODE == 0) {
                int part = cg >> 10;          // 0:q 1:k 2:v  (E=1024)
                int e = cg & 1023;
                int h = e >> 6, d = e & 63;
                int b = r >> 11, s = r & 2047; // S=2048
                float* dst = (part == 0) ? Qd : (part == 1) ? Kd : Vd;
                *(float4*)&dst[(((b*Hh + h)*Ss) + s)*Dd + d] = v;
            } else {
                *(float4*)&Cout[(size_t)r * N + cg] = v;
            }
        }
    }
}

// ---------------------------------------------------------------------------
// fp32 flash attention, causal. Br=Bc=64, D=64, 256 threads, 4x4 per thread.
// Q,K in smem d-major ([d][row], stride 68) -> 1 LDS.128 per operand per step.
// scale = 1/(sqrt(64)*2) = 1/16 ; masked entries set to -10000 (matches ref).
// ---------------------------------------------------------------------------
__global__ void __launch_bounds__(256)
flash_kernel(const float* __restrict__ Q, const float* __restrict__ K,
             const float* __restrict__ V, float* __restrict__ O)
{
    extern __shared__ float sm[];
    float* Qt = sm;                  // [64][68] d-major
    float* Kt = sm + 64*68;          // [64][68] d-major
    float* Vs = sm + 2*64*68;        // [k][68]  natural
    float* Ps = sm + 3*64*68;        // [m][68]  natural

    const int tid = threadIdx.x;
    const int tx = tid & 15;         // 4 cols each
    const int ty = tid >> 4;         // 4 rows each
    const int qt = blockIdx.x;       // 0..31
    const int bh = blockIdx.y;       // 0..31
    const int q0 = qt * 64;

    // load Q tile transposed (once)
    const float* Qb = Q + ((size_t)bh * Ss + q0) * Dd;
    #pragma unroll
    for (int i = 0; i < 4; i++) {
        int f = tid + i*256;
        int r = f >> 4, d4 = (f & 15) * 4;
        float4 v = *(const float4*)(Qb + r*Dd + d4);
        Qt[(d4+0)*68 + r] = v.x;
        Qt[(d4+1)*68 + r] = v.y;
        Qt[(d4+2)*68 + r] = v.z;
        Qt[(d4+3)*68 + r] = v.w;
    }

    float m_[4], l_[4], o[4][4];
    #pragma unroll
    for (int i = 0; i < 4; i++) {
        m_[i] = -1e30f; l_[i] = 0.f;
        #pragma unroll
        for (int j = 0; j < 4; j++) o[i][j] = 0.f;
    }
    __syncthreads();

    for (int kt = 0; kt <= qt; kt++) {
        const int k0 = kt * 64;
        const float* Kb = K + ((size_t)bh * Ss + k0) * Dd;
        const float* Vb = V + ((size_t)bh * Ss + k0) * Dd;
        #pragma unroll
        for (int i = 0; i < 4; i++) {
            int f = tid + i*256;
            int r = f >> 4, d4 = (f & 15) * 4;
            float4 kv = *(const float4*)(Kb + r*Dd + d4);
            Kt[(d4+0)*68 + r] = kv.x;
            Kt[(d4+1)*68 + r] = kv.y;
            Kt[(d4+2)*68 + r] = kv.z;
            Kt[(d4+3)*68 + r] = kv.w;
            float4 vv = *(const float4*)(Vb + r*Dd + d4);
            *(float4*)&Vs[r*68 + d4] = vv;
        }
        __syncthreads();

        // S = Q K^T  (4x4 per thread)
        float s[4][4];
        #pragma unroll
        for (int i = 0; i < 4; i++)
            #pragma unroll
            for (int j = 0; j < 4; j++) s[i][j] = 0.f;

        #pragma unroll 16
        for (int d = 0; d < 64; d++) {
            float4 qv = *(float4*)&Qt[d*68 + ty*4];
            float4 kv = *(float4*)&Kt[d*68 + tx*4];
            float qa[4] = {qv.x, qv.y, qv.z, qv.w};
            float ka[4] = {kv.x, kv.y, kv.z, kv.w};
            #pragma unroll
            for (int i = 0; i < 4; i++)
                #pragma unroll
                for (int j = 0; j < 4; j++)
                    s[i][j] = fmaf(qa[i], ka[j], s[i][j]);
        }

        const float sc = 1.0f / 16.0f;   // 1/(sqrt(64)*layer_idx)
        const bool diag = (kt == qt);
        #pragma unroll
        for (int i = 0; i < 4; i++)
            #pragma unroll
            for (int j = 0; j < 4; j++) {
                s[i][j] *= sc;
                if (diag && (k0 + tx*4 + j > q0 + ty*4 + i)) s[i][j] = -10000.0f;
            }

        // online softmax (rows shared by the 16 tx-threads; shfl within 16-group)
        #pragma unroll
        for (int i = 0; i < 4; i++) {
            float rm = fmaxf(fmaxf(s[i][0], s[i][1]), fmaxf(s[i][2], s[i][3]));
            #pragma unroll
            for (int off = 8; off > 0; off >>= 1)
                rm = fmaxf(rm, __shfl_xor_sync(0xffffffffu, rm, off));
            float mn = fmaxf(m_[i], rm);
            float c = __expf(m_[i] - mn);
            m_[i] = mn;
            float rs = 0.f;
            #pragma unroll
            for (int j = 0; j < 4; j++) {
                s[i][j] = __expf(s[i][j] - mn);
                rs += s[i][j];
            }
            #pragma unroll
            for (int off = 8; off > 0; off >>= 1)
                rs += __shfl_xor_sync(0xffffffffu, rs, off);
            l_[i] = l_[i] * c + rs;
            #pragma unroll
            for (int j = 0; j < 4; j++) o[i][j] *= c;
        }

        #pragma unroll
        for (int i = 0; i < 4; i++)
            *(float4*)&Ps[(ty*4+i)*68 + tx*4] =
                make_float4(s[i][0], s[i][1], s[i][2], s[i][3]);
        __syncthreads();

        // O += P @ V
        #pragma unroll 16
        for (int k = 0; k < 64; k++) {
            float4 vv = *(float4*)&Vs[k*68 + tx*4];
            #pragma unroll
            for (int i = 0; i < 4; i++) {
                float p = Ps[(ty*4+i)*68 + k];
                o[i][0] = fmaf(p, vv.x, o[i][0]);
                o[i][1] = fmaf(p, vv.y, o[i][1]);
                o[i][2] = fmaf(p, vv.z, o[i][2]);
                o[i][3] = fmaf(p, vv.w, o[i][3]);
            }
        }
        __syncthreads();
    }

    // finalize + write merged-head layout [B,S,E]
    const int b = bh >> 4, h = bh & 15;
    #pragma unroll
    for (int i = 0; i < 4; i++) {
        float inv = 1.0f / l_[i];
        int srow = q0 + ty*4 + i;
        float4 v = make_float4(o[i][0]*inv, o[i][1]*inv, o[i][2]*inv, o[i][3]*inv);
        *(float4*)&O[((size_t)(b*Ss + srow)) * Ee + h*64 + tx*4] = v;
    }
}

// ---------------------------------------------------------------------------
extern "C" void kernel_launch(void* const* d_in, const int* in_sizes, int n_in,
                              void* d_out, int out_size)
{
    const float* hs     = (const float*)d_in[0];  // [B,S,E]
    const float* w_attn = (const float*)d_in[1];  // [E,3E]
    const float* b_attn = (const float*)d_in[2];  // [3E]
    const float* w_proj = (const float*)d_in[3];  // [E,E]
    const float* b_proj = (const float*)d_in[4];  // [E]
    float* out = (float*)d_out;                   // [B,S,E]

    float *qp, *kp, *vp, *aop;
    cudaGetSymbolAddress((void**)&qp,  g_q);
    cudaGetSymbolAddress((void**)&kp,  g_k);
    cudaGetSymbolAddress((void**)&vp,  g_v);
    cudaGetSymbolAddress((void**)&aop, g_ao);

    // 1) QKV GEMM + scatter into [B,H,S,D]
    sgemm_kernel<0><<<dim3(3*Ee/128, (Bb*Ss)/128), 256>>>(
        hs, w_attn, b_attn, nullptr, qp, kp, vp, Bb*Ss, 3*Ee, Ee);

    // 2) causal flash attention
    const int flash_smem = 4 * 64 * 68 * (int)sizeof(float);  // 69632 B
    cudaFuncSetAttribute(flash_kernel,
                         cudaFuncAttributeMaxDynamicSharedMemorySize, flash_smem);
    flash_kernel<<<dim3(Ss/64, BHh), 256, flash_smem>>>(qp, kp, vp, aop);

    // 3) output projection -> d_out
    sgemm_kernel<1><<<dim3(Ee/128, (Bb*Ss)/128), 256>>>(
        aop, w_proj, b_proj, out, nullptr, nullptr, nullptr, Bb*Ss, Ee, Ee);
}